// round 3
// baseline (speedup 1.0000x reference)
#include <cuda_runtime.h>
#include <math.h>

static constexpr int Hdim = 1024;
static constexpr int Vdim = 50257;
static constexpr int Bdim = 64;
static constexpr int Tdim = 512;

// ---------------- scratch (static device allocations only) ----------------
__device__ float g_gi[Bdim * 3 * Hdim];
__device__ float g_gh[Bdim * 3 * Hdim];
__device__ float g_concat[Bdim * 2 * Hdim];   // [:, :H] = h, [:, H:] = context
__device__ float g_g[Bdim * Hdim];            // h @ W_a
__device__ float g_s0[Bdim];                  // h . b_a
__device__ float g_scores[Bdim * Tdim];       // scores -> attn weights (in place)
__device__ float g_ctxp[4 * Bdim * Hdim];     // context partials (t-split)
__device__ float g_co[Bdim * Hdim];           // concat_output

// ---------------- f32x2 helpers ----------------
__device__ __forceinline__ unsigned long long pack_dup(float a) {
    unsigned long long r;
    asm("mov.b64 %0, {%1, %1};" : "=l"(r) : "f"(a));
    return r;
}
__device__ __forceinline__ void fma2(unsigned long long& d, unsigned long long a,
                                     unsigned long long b) {
    asm("fma.rn.f32x2 %0, %1, %2, %3;" : "=l"(d) : "l"(a), "l"(b), "l"(d));
}
__device__ __forceinline__ float2 unpack2(unsigned long long v) {
    float2 f;
    f.x = __uint_as_float((unsigned)(v & 0xFFFFFFFFull));
    f.y = __uint_as_float((unsigned)(v >> 32));
    return f;
}

// ---------------- C[64,N] = A[64,K] @ W[N,K]^T (+bias, opt tanh) ----------------
// BM=64 (all rows), BN=64, BK=32, 256 threads, 4x4 microtile, f32x2 inner.
// Optional row gather on A (embedding lookup). Optional second parameter set
// selected by blockIdx.y==1 (lets G1/G2 of the GRU run as one launch).
template <bool TANH>
__global__ void __launch_bounds__(256)
gemm64_nt(const float* __restrict__ A, const int* __restrict__ gidx,
          const float* __restrict__ W, const float* __restrict__ bias,
          float* __restrict__ C,
          int lda, int ldc, int N, int K,
          const float* A2, const float* W2, const float* bias2, float* C2)
{
    if (blockIdx.y == 1) { A = A2; W = W2; bias = bias2; C = C2; gidx = nullptr; }

    __shared__ float As[32][66];   // [k][m], +2 pad keeps float2 reads 8B-aligned
    __shared__ float Ws[32][66];   // [k][j]

    const int tid = threadIdx.x;
    const int tx = tid & 15, ty = tid >> 4;
    const int j0 = blockIdx.x * 64;

    unsigned long long acc[4][2];
#pragma unroll
    for (int i = 0; i < 4; i++) { acc[i][0] = 0ull; acc[i][1] = 0ull; }

    const int mload = tid >> 3;   // 0..31
    const int qload = tid & 7;    // 0..7  (float4 chunk within 32-wide K tile)

    for (int k0 = 0; k0 < K; k0 += 32) {
#pragma unroll
        for (int it = 0; it < 2; it++) {
            int mm = mload + 32 * it;
            const float* arow = gidx ? (A + (size_t)gidx[mm] * lda)
                                     : (A + (size_t)mm * lda);
            float4 v = *reinterpret_cast<const float4*>(arow + k0 + qload * 4);
            As[qload * 4 + 0][mm] = v.x; As[qload * 4 + 1][mm] = v.y;
            As[qload * 4 + 2][mm] = v.z; As[qload * 4 + 3][mm] = v.w;

            int gj = j0 + mm;
            float4 w4 = make_float4(0.f, 0.f, 0.f, 0.f);
            if (gj < N)
                w4 = *reinterpret_cast<const float4*>(W + (size_t)gj * K + k0 + qload * 4);
            Ws[qload * 4 + 0][mm] = w4.x; Ws[qload * 4 + 1][mm] = w4.y;
            Ws[qload * 4 + 2][mm] = w4.z; Ws[qload * 4 + 3][mm] = w4.w;
        }
        __syncthreads();
#pragma unroll
        for (int kk = 0; kk < 32; kk++) {
            float2 a01 = *reinterpret_cast<const float2*>(&As[kk][ty * 4]);
            float2 a23 = *reinterpret_cast<const float2*>(&As[kk][ty * 4 + 2]);
            unsigned long long b0 =
                __double_as_longlong(*reinterpret_cast<const double*>(&Ws[kk][tx * 4]));
            unsigned long long b1 =
                __double_as_longlong(*reinterpret_cast<const double*>(&Ws[kk][tx * 4 + 2]));
            unsigned long long a0 = pack_dup(a01.x), a1 = pack_dup(a01.y);
            unsigned long long a2 = pack_dup(a23.x), a3 = pack_dup(a23.y);
            fma2(acc[0][0], a0, b0); fma2(acc[0][1], a0, b1);
            fma2(acc[1][0], a1, b0); fma2(acc[1][1], a1, b1);
            fma2(acc[2][0], a2, b0); fma2(acc[2][1], a2, b1);
            fma2(acc[3][0], a3, b0); fma2(acc[3][1], a3, b1);
        }
        __syncthreads();
    }

#pragma unroll
    for (int i = 0; i < 4; i++) {
        int m = ty * 4 + i;
        float2 c01 = unpack2(acc[i][0]);
        float2 c23 = unpack2(acc[i][1]);
        float vals[4] = {c01.x, c01.y, c23.x, c23.y};
#pragma unroll
        for (int jj = 0; jj < 4; jj++) {
            int j = j0 + tx * 4 + jj;
            if (j < N) {
                float r = vals[jj] + (bias ? bias[j] : 0.0f);
                if (TANH) r = tanhf(r);
                C[(size_t)m * ldc + j] = r;
            }
        }
    }
}

// ---------------- C[64,N] = A[64,K] @ W[K,N] (no transpose, no bias) ----------------
__global__ void __launch_bounds__(256)
gemm64_nn(const float* __restrict__ A, const float* __restrict__ W,
          float* __restrict__ C, int lda, int ldc, int N, int K)
{
    __shared__ float As[32][66];
    __shared__ float Ws[32][66];

    const int tid = threadIdx.x;
    const int tx = tid & 15, ty = tid >> 4;
    const int j0 = blockIdx.x * 64;

    unsigned long long acc[4][2];
#pragma unroll
    for (int i = 0; i < 4; i++) { acc[i][0] = 0ull; acc[i][1] = 0ull; }

    const int mload = tid >> 3;
    const int qload = tid & 7;
    const int jq = tid & 15;    // j chunk (4 floats)
    const int kr = tid >> 4;    // 0..15

    for (int k0 = 0; k0 < K; k0 += 32) {
#pragma unroll
        for (int it = 0; it < 2; it++) {
            int mm = mload + 32 * it;
            float4 v = *reinterpret_cast<const float4*>(A + (size_t)mm * lda + k0 + qload * 4);
            As[qload * 4 + 0][mm] = v.x; As[qload * 4 + 1][mm] = v.y;
            As[qload * 4 + 2][mm] = v.z; As[qload * 4 + 3][mm] = v.w;

            int kk = kr + 16 * it;
            float4 w4 = *reinterpret_cast<const float4*>(W + (size_t)(k0 + kk) * N + j0 + jq * 4);
            *reinterpret_cast<float2*>(&Ws[kk][jq * 4])     = make_float2(w4.x, w4.y);
            *reinterpret_cast<float2*>(&Ws[kk][jq * 4 + 2]) = make_float2(w4.z, w4.w);
        }
        __syncthreads();
#pragma unroll
        for (int kk = 0; kk < 32; kk++) {
            float2 a01 = *reinterpret_cast<const float2*>(&As[kk][ty * 4]);
            float2 a23 = *reinterpret_cast<const float2*>(&As[kk][ty * 4 + 2]);
            unsigned long long b0 =
                __double_as_longlong(*reinterpret_cast<const double*>(&Ws[kk][tx * 4]));
            unsigned long long b1 =
                __double_as_longlong(*reinterpret_cast<const double*>(&Ws[kk][tx * 4 + 2]));
            unsigned long long a0 = pack_dup(a01.x), a1 = pack_dup(a01.y);
            unsigned long long a2 = pack_dup(a23.x), a3 = pack_dup(a23.y);
            fma2(acc[0][0], a0, b0); fma2(acc[0][1], a0, b1);
            fma2(acc[1][0], a1, b0); fma2(acc[1][1], a1, b1);
            fma2(acc[2][0], a2, b0); fma2(acc[2][1], a2, b1);
            fma2(acc[3][0], a3, b0); fma2(acc[3][1], a3, b1);
        }
        __syncthreads();
    }

#pragma unroll
    for (int i = 0; i < 4; i++) {
        int m = ty * 4 + i;
        float2 c01 = unpack2(acc[i][0]);
        float2 c23 = unpack2(acc[i][1]);
        float vals[4] = {c01.x, c01.y, c23.x, c23.y};
#pragma unroll
        for (int jj = 0; jj < 4; jj++) {
            int j = j0 + tx * 4 + jj;
            C[(size_t)m * ldc + j] = vals[jj];
        }
    }
}

// ---------------- GRU gate elementwise ----------------
__global__ void gate_kernel(const float* __restrict__ h0, float* __restrict__ hid_out)
{
    int i = blockIdx.x * blockDim.x + threadIdx.x;   // 0..65535
    int b = i >> 10, c = i & 1023;
    const float* gi = g_gi + (size_t)b * 3072;
    const float* gh = g_gh + (size_t)b * 3072;
    float r = 1.f / (1.f + __expf(-(gi[c] + gh[c])));
    float z = 1.f / (1.f + __expf(-(gi[1024 + c] + gh[1024 + c])));
    float n = tanhf(gi[2048 + c] + r * gh[2048 + c]);
    float hv = (1.f - z) * n + z * h0[i];
    g_concat[(size_t)b * 2048 + c] = hv;
    hid_out[i] = hv;
}

// ---------------- s0[b] = h[b] . b_a ----------------
__global__ void s0_kernel(const float* __restrict__ ba)
{
    int b = blockIdx.x;
    float p = 0.f;
    for (int h = threadIdx.x; h < 1024; h += 128)
        p += g_concat[(size_t)b * 2048 + h] * ba[h];
#pragma unroll
    for (int o = 16; o; o >>= 1) p += __shfl_xor_sync(0xffffffffu, p, o);
    __shared__ float red[4];
    int wid = threadIdx.x >> 5, lane = threadIdx.x & 31;
    if (lane == 0) red[wid] = p;
    __syncthreads();
    if (threadIdx.x == 0) g_s0[b] = red[0] + red[1] + red[2] + red[3];
}

// ---------------- scores[b,t] = enc[b,t,:] . g[b,:] + s0[b] ----------------
// One warp per (b,t); 64 consecutive blocks share b so g[b] stays L1-hot.
__global__ void __launch_bounds__(256) scores_kernel(const float* __restrict__ enc)
{
    int b = blockIdx.x >> 6;
    int t = ((blockIdx.x & 63) << 3) | (threadIdx.x >> 5);
    int lane = threadIdx.x & 31;
    const float4* e  = reinterpret_cast<const float4*>(enc + ((size_t)b * 512 + t) * 1024);
    const float4* gv = reinterpret_cast<const float4*>(g_g + (size_t)b * 1024);
    float acc = 0.f;
#pragma unroll
    for (int i = 0; i < 8; i++) {
        float4 ev = e[lane + 32 * i];
        float4 gg = gv[lane + 32 * i];
        acc += ev.x * gg.x + ev.y * gg.y + ev.z * gg.z + ev.w * gg.w;
    }
#pragma unroll
    for (int o = 16; o; o >>= 1) acc += __shfl_xor_sync(0xffffffffu, acc, o);
    if (lane == 0) g_scores[b * 512 + t] = acc + g_s0[b];
}

// ---------------- softmax over t (per b), in place ----------------
__global__ void __launch_bounds__(256) softmax_kernel()
{
    int b = blockIdx.x, tid = threadIdx.x;
    int wid = tid >> 5, lane = tid & 31;
    __shared__ float red[8];
    __shared__ float bval;

    float2 v = *reinterpret_cast<float2*>(&g_scores[b * 512 + tid * 2]);
    float mx = fmaxf(v.x, v.y);
#pragma unroll
    for (int o = 16; o; o >>= 1) mx = fmaxf(mx, __shfl_xor_sync(0xffffffffu, mx, o));
    if (lane == 0) red[wid] = mx;
    __syncthreads();
    if (tid == 0) {
        float m = red[0];
#pragma unroll
        for (int i = 1; i < 8; i++) m = fmaxf(m, red[i]);
        bval = m;
    }
    __syncthreads();
    float M = bval;
    float e0 = __expf(v.x - M), e1 = __expf(v.y - M);
    float s = e0 + e1;
    __syncthreads();   // red reuse safety
#pragma unroll
    for (int o = 16; o; o >>= 1) s += __shfl_xor_sync(0xffffffffu, s, o);
    if (lane == 0) red[wid] = s;
    __syncthreads();
    if (tid == 0) {
        float t = 0.f;
#pragma unroll
        for (int i = 0; i < 8; i++) t += red[i];
        bval = t;
    }
    __syncthreads();
    float inv = 1.f / bval;
    *reinterpret_cast<float2*>(&g_scores[b * 512 + tid * 2]) = make_float2(e0 * inv, e1 * inv);
}

// ---------------- context partials: sum over a 128-t chunk ----------------
__global__ void __launch_bounds__(256) context_kernel(const float* __restrict__ enc)
{
    int b = blockIdx.x, half = blockIdx.y, zc = blockIdx.z;
    __shared__ float w[128];
    if (threadIdx.x < 128) w[threadIdx.x] = g_scores[b * 512 + zc * 128 + threadIdx.x];
    __syncthreads();
    int h = half * 512 + threadIdx.x * 2;
    const float* ep = enc + (size_t)b * 512 * 1024 + (size_t)zc * 128 * 1024 + h;
    float2 acc = make_float2(0.f, 0.f);
#pragma unroll 4
    for (int t = 0; t < 128; t++) {
        float2 e = *reinterpret_cast<const float2*>(ep + (size_t)t * 1024);
        acc.x += w[t] * e.x;
        acc.y += w[t] * e.y;
    }
    *reinterpret_cast<float2*>(&g_ctxp[(size_t)(zc * 64 + b) * 1024 + h]) = acc;
}

__global__ void __launch_bounds__(256) ctx_reduce_kernel()
{
    int b = blockIdx.x;
    int h = threadIdx.x * 4;
    float4 s = make_float4(0.f, 0.f, 0.f, 0.f);
#pragma unroll
    for (int z = 0; z < 4; z++) {
        float4 p = *reinterpret_cast<float4*>(&g_ctxp[(size_t)(z * 64 + b) * 1024 + h]);
        s.x += p.x; s.y += p.y; s.z += p.z; s.w += p.w;
    }
    *reinterpret_cast<float4*>(&g_concat[(size_t)b * 2048 + 1024 + h]) = s;
}

// ---------------- launch ----------------
extern "C" void kernel_launch(void* const* d_in, const int* in_sizes, int n_in,
                              void* d_out, int out_size)
{
    const int*   seq = (const int*)d_in[0];
    const float* h0  = (const float*)d_in[1];
    const float* enc = (const float*)d_in[2];
    const float* emb = (const float*)d_in[3];
    const float* Wih = (const float*)d_in[4];
    const float* Whh = (const float*)d_in[5];
    const float* bih = (const float*)d_in[6];
    const float* bhh = (const float*)d_in[7];
    const float* Wa  = (const float*)d_in[8];
    const float* ba  = (const float*)d_in[9];
    const float* Wc  = (const float*)d_in[10];
    const float* bc  = (const float*)d_in[11];
    const float* Wo  = (const float*)d_in[12];
    const float* bo  = (const float*)d_in[13];

    float* out = (float*)d_out;                       // [B, V]
    float* hid = out + (size_t)Bdim * Vdim;           // [1, B, H]

    float *gi, *gh, *concat, *gg, *co;
    cudaGetSymbolAddress((void**)&gi, g_gi);
    cudaGetSymbolAddress((void**)&gh, g_gh);
    cudaGetSymbolAddress((void**)&concat, g_concat);
    cudaGetSymbolAddress((void**)&gg, g_g);
    cudaGetSymbolAddress((void**)&co, g_co);

    // G1 (gi = emb[seq] @ Wih^T + bih) and G2 (gh = h0 @ Whh^T + bhh), one launch
    gemm64_nt<false><<<dim3(48, 2), 256>>>(emb, seq, Wih, bih, gi,
                                           Hdim, 3 * Hdim, 3 * Hdim, Hdim,
                                           h0, Whh, bhh, gh);
    // GRU gates -> h (writes hidden output + left half of concat)
    gate_kernel<<<256, 256>>>(h0, hid);
    // s0 = h . b_a
    s0_kernel<<<64, 128>>>(ba);
    // g = h @ W_a  (NN)
    gemm64_nn<<<16, 256>>>(concat, Wa, gg, 2 * Hdim, Hdim, Hdim, Hdim);
    // scores
    scores_kernel<<<4096, 256>>>(enc);
    // softmax -> attention weights (in place)
    softmax_kernel<<<64, 256>>>();
    // context (t-split x4) + reduce into right half of concat
    context_kernel<<<dim3(64, 2, 4), 256>>>(enc);
    ctx_reduce_kernel<<<64, 256>>>();
    // concat_output = tanh(concat @ Wc^T + bc)
    gemm64_nt<true><<<16, 256>>>(concat, nullptr, Wc, bc, co,
                                 2 * Hdim, Hdim, Hdim, 2 * Hdim,
                                 nullptr, nullptr, nullptr, nullptr);
    // output = co @ Wo^T + bo
    gemm64_nt<false><<<786, 256>>>(co, nullptr, Wo, bo, out,
                                   Hdim, Vdim, Vdim, Hdim,
                                   nullptr, nullptr, nullptr, nullptr);
}

// round 8
// speedup vs baseline: 2.3755x; 2.3755x over previous
#include <cuda_runtime.h>
#include <cuda_bf16.h>
#include <math.h>

static constexpr int Hdim = 1024;
static constexpr int Vdim = 50257;
static constexpr int Bdim = 64;
static constexpr int Tdim = 512;
static constexpr int NSPLIT = 8;

// ---------------- scratch (static device arrays only) ----------------
__device__ float g_gip[NSPLIT * Bdim * 3 * Hdim];  // gi partials
__device__ float g_ghp[NSPLIT * Bdim * 3 * Hdim];  // gh partials
__device__ float g_gp [NSPLIT * Bdim * Hdim];      // (h@W_a) partials
__device__ float g_c1p[NSPLIT * Bdim * Hdim];      // (concat@Wc^T) partials
__device__ float g_concat[Bdim * 2 * Hdim];        // [:, :H] = h, [:, H:] = context
__device__ float g_g[Bdim * Hdim];                 // h @ W_a
__device__ float g_s0[Bdim];                       // h . b_a
__device__ float g_scores[Bdim * Tdim];            // scores -> attn weights (in place)
__device__ float g_ctxp[4 * Bdim * Hdim];          // context partials (t-split)
__device__ float g_co[Bdim * Hdim];                // concat_output
__device__ uint4 g_afh[64 * 4 * 32];               // co hi bf16 mma A-fragments
__device__ uint4 g_afl[64 * 4 * 32];               // co lo bf16 mma A-fragments

// ---------------- f32x2 helpers ----------------
__device__ __forceinline__ unsigned long long pack_dup(float a) {
    unsigned long long r;
    asm("mov.b64 %0, {%1, %1};" : "=l"(r) : "f"(a));
    return r;
}
__device__ __forceinline__ void fma2(unsigned long long& d, unsigned long long a,
                                     unsigned long long b) {
    asm("fma.rn.f32x2 %0, %1, %2, %3;" : "=l"(d) : "l"(a), "l"(b), "l"(d));
}
__device__ __forceinline__ float2 unpack2(unsigned long long v) {
    float2 f;
    f.x = __uint_as_float((unsigned)(v & 0xFFFFFFFFull));
    f.y = __uint_as_float((unsigned)(v >> 32));
    return f;
}

// ---------------- bf16 split helpers ----------------
__device__ __forceinline__ void bf16_split2(float x, float y, unsigned& hi, unsigned& lo) {
    __nv_bfloat16 hx = __float2bfloat16(x);
    __nv_bfloat16 hy = __float2bfloat16(y);
    __nv_bfloat16 lx = __float2bfloat16(x - __bfloat162float(hx));
    __nv_bfloat16 ly = __float2bfloat16(y - __bfloat162float(hy));
    hi = (unsigned)__bfloat16_as_ushort(hx) | ((unsigned)__bfloat16_as_ushort(hy) << 16);
    lo = (unsigned)__bfloat16_as_ushort(lx) | ((unsigned)__bfloat16_as_ushort(ly) << 16);
}

__device__ __forceinline__ void mma_bf16(float (&d)[4], const uint4& a,
                                         unsigned b0, unsigned b1) {
    asm volatile(
        "mma.sync.aligned.m16n8k16.row.col.f32.bf16.bf16.f32 "
        "{%0,%1,%2,%3}, {%4,%5,%6,%7}, {%8,%9}, {%0,%1,%2,%3};"
        : "+f"(d[0]), "+f"(d[1]), "+f"(d[2]), "+f"(d[3])
        : "r"(a.x), "r"(a.y), "r"(a.z), "r"(a.w), "r"(b0), "r"(b1));
}

// ============ split-K NT partial GEMM: Cp[z] = A[64,Kslice] @ W[N,K]^T slice ============
__global__ void __launch_bounds__(256)
gemm_nt_part(const float* __restrict__ A, const int* __restrict__ gidx,
             const float* __restrict__ W, float* __restrict__ Cp,
             int lda, int N, int K, int Kper,
             const float* A2, const float* W2, float* Cp2)
{
    if (blockIdx.y == 1) { A = A2; W = W2; Cp = Cp2; gidx = nullptr; }

    __shared__ float As[32][66];
    __shared__ float Ws[32][66];

    const int tid = threadIdx.x;
    const int tx = tid & 15, ty = tid >> 4;
    const int j0 = blockIdx.x * 64;
    const int kb = blockIdx.z * Kper;

    unsigned long long acc[4][2];
#pragma unroll
    for (int i = 0; i < 4; i++) { acc[i][0] = 0ull; acc[i][1] = 0ull; }

    const int mload = tid >> 3;
    const int qload = tid & 7;

    for (int k0 = kb; k0 < kb + Kper; k0 += 32) {
#pragma unroll
        for (int it = 0; it < 2; it++) {
            int mm = mload + 32 * it;
            const float* arow = gidx ? (A + (size_t)gidx[mm] * lda)
                                     : (A + (size_t)mm * lda);
            float4 v = *reinterpret_cast<const float4*>(arow + k0 + qload * 4);
            As[qload * 4 + 0][mm] = v.x; As[qload * 4 + 1][mm] = v.y;
            As[qload * 4 + 2][mm] = v.z; As[qload * 4 + 3][mm] = v.w;

            float4 w4 = *reinterpret_cast<const float4*>(W + (size_t)(j0 + mm) * K + k0 + qload * 4);
            Ws[qload * 4 + 0][mm] = w4.x; Ws[qload * 4 + 1][mm] = w4.y;
            Ws[qload * 4 + 2][mm] = w4.z; Ws[qload * 4 + 3][mm] = w4.w;
        }
        __syncthreads();
#pragma unroll
        for (int kk = 0; kk < 32; kk++) {
            float2 a01 = *reinterpret_cast<const float2*>(&As[kk][ty * 4]);
            float2 a23 = *reinterpret_cast<const float2*>(&As[kk][ty * 4 + 2]);
            unsigned long long b0 =
                __double_as_longlong(*reinterpret_cast<const double*>(&Ws[kk][tx * 4]));
            unsigned long long b1 =
                __double_as_longlong(*reinterpret_cast<const double*>(&Ws[kk][tx * 4 + 2]));
            unsigned long long a0 = pack_dup(a01.x), a1 = pack_dup(a01.y);
            unsigned long long a2 = pack_dup(a23.x), a3 = pack_dup(a23.y);
            fma2(acc[0][0], a0, b0); fma2(acc[0][1], a0, b1);
            fma2(acc[1][0], a1, b0); fma2(acc[1][1], a1, b1);
            fma2(acc[2][0], a2, b0); fma2(acc[2][1], a2, b1);
            fma2(acc[3][0], a3, b0); fma2(acc[3][1], a3, b1);
        }
        __syncthreads();
    }

    float* base = Cp + (size_t)blockIdx.z * 64 * N;
#pragma unroll
    for (int i = 0; i < 4; i++) {
        int m = ty * 4 + i;
        float2 c01 = unpack2(acc[i][0]);
        float2 c23 = unpack2(acc[i][1]);
        float4 v = make_float4(c01.x, c01.y, c23.x, c23.y);
        *reinterpret_cast<float4*>(base + (size_t)m * N + j0 + tx * 4) = v;
    }
}

// ============ split-K NN partial GEMM: Cp[z] = A[64,Kslice] @ W[Kslice,N] ============
__global__ void __launch_bounds__(256)
gemm_nn_part(const float* __restrict__ A, const float* __restrict__ W,
             float* __restrict__ Cp, int lda, int N, int Kper)
{
    __shared__ float As[32][66];
    __shared__ float Ws[32][66];

    const int tid = threadIdx.x;
    const int tx = tid & 15, ty = tid >> 4;
    const int j0 = blockIdx.x * 64;
    const int kb = blockIdx.z * Kper;

    unsigned long long acc[4][2];
#pragma unroll
    for (int i = 0; i < 4; i++) { acc[i][0] = 0ull; acc[i][1] = 0ull; }

    const int mload = tid >> 3;
    const int qload = tid & 7;
    const int jq = tid & 15;
    const int kr = tid >> 4;

    for (int k0 = kb; k0 < kb + Kper; k0 += 32) {
#pragma unroll
        for (int it = 0; it < 2; it++) {
            int mm = mload + 32 * it;
            float4 v = *reinterpret_cast<const float4*>(A + (size_t)mm * lda + k0 + qload * 4);
            As[qload * 4 + 0][mm] = v.x; As[qload * 4 + 1][mm] = v.y;
            As[qload * 4 + 2][mm] = v.z; As[qload * 4 + 3][mm] = v.w;

            int kk = kr + 16 * it;
            float4 w4 = *reinterpret_cast<const float4*>(W + (size_t)(k0 + kk) * N + j0 + jq * 4);
            *reinterpret_cast<float2*>(&Ws[kk][jq * 4])     = make_float2(w4.x, w4.y);
            *reinterpret_cast<float2*>(&Ws[kk][jq * 4 + 2]) = make_float2(w4.z, w4.w);
        }
        __syncthreads();
#pragma unroll
        for (int kk = 0; kk < 32; kk++) {
            float2 a01 = *reinterpret_cast<const float2*>(&As[kk][ty * 4]);
            float2 a23 = *reinterpret_cast<const float2*>(&As[kk][ty * 4 + 2]);
            unsigned long long b0 =
                __double_as_longlong(*reinterpret_cast<const double*>(&Ws[kk][tx * 4]));
            unsigned long long b1 =
                __double_as_longlong(*reinterpret_cast<const double*>(&Ws[kk][tx * 4 + 2]));
            unsigned long long a0 = pack_dup(a01.x), a1 = pack_dup(a01.y);
            unsigned long long a2 = pack_dup(a23.x), a3 = pack_dup(a23.y);
            fma2(acc[0][0], a0, b0); fma2(acc[0][1], a0, b1);
            fma2(acc[1][0], a1, b0); fma2(acc[1][1], a1, b1);
            fma2(acc[2][0], a2, b0); fma2(acc[2][1], a2, b1);
            fma2(acc[3][0], a3, b0); fma2(acc[3][1], a3, b1);
        }
        __syncthreads();
    }

    float* base = Cp + (size_t)blockIdx.z * 64 * N;
#pragma unroll
    for (int i = 0; i < 4; i++) {
        int m = ty * 4 + i;
        float2 c01 = unpack2(acc[i][0]);
        float2 c23 = unpack2(acc[i][1]);
        float4 v = make_float4(c01.x, c01.y, c23.x, c23.y);
        *reinterpret_cast<float4*>(base + (size_t)m * N + j0 + tx * 4) = v;
    }
}

// ---------------- GRU gates: reduce split-K partials + bias + nonlinearity ----------------
__global__ void gate_kernel(const float* __restrict__ h0,
                            const float* __restrict__ bih, const float* __restrict__ bhh,
                            float* __restrict__ hid_out)
{
    int i = blockIdx.x * blockDim.x + threadIdx.x;   // 0..65535
    int b = i >> 10, c = i & 1023;
    float gir = bih[c], giz = bih[1024 + c], gin = bih[2048 + c];
    float ghr = bhh[c], ghz = bhh[1024 + c], ghn = bhh[2048 + c];
#pragma unroll
    for (int s = 0; s < NSPLIT; s++) {
        const float* gp = g_gip + (size_t)(s * 64 + b) * 3072;
        const float* hp = g_ghp + (size_t)(s * 64 + b) * 3072;
        gir += gp[c]; giz += gp[1024 + c]; gin += gp[2048 + c];
        ghr += hp[c]; ghz += hp[1024 + c]; ghn += hp[2048 + c];
    }
    float r = 1.f / (1.f + __expf(-(gir + ghr)));
    float z = 1.f / (1.f + __expf(-(giz + ghz)));
    float n = tanhf(gin + r * ghn);
    float hv = (1.f - z) * n + z * h0[i];
    g_concat[(size_t)b * 2048 + c] = hv;
    hid_out[i] = hv;
}

// ---------------- s0[b] = h[b] . b_a ----------------
__global__ void s0_kernel(const float* __restrict__ ba)
{
    int b = blockIdx.x;
    float p = 0.f;
    for (int h = threadIdx.x; h < 1024; h += 128)
        p += g_concat[(size_t)b * 2048 + h] * ba[h];
#pragma unroll
    for (int o = 16; o; o >>= 1) p += __shfl_xor_sync(0xffffffffu, p, o);
    __shared__ float red[4];
    int wid = threadIdx.x >> 5, lane = threadIdx.x & 31;
    if (lane == 0) red[wid] = p;
    __syncthreads();
    if (threadIdx.x == 0) g_s0[b] = red[0] + red[1] + red[2] + red[3];
}

// ---------------- reduce g partials -> g_g ----------------
__global__ void __launch_bounds__(256) g_reduce_kernel()
{
    int b = blockIdx.x;
    int h = threadIdx.x * 4;
    float4 s = make_float4(0.f, 0.f, 0.f, 0.f);
#pragma unroll
    for (int z = 0; z < NSPLIT; z++) {
        float4 p = *reinterpret_cast<float4*>(&g_gp[(size_t)(z * 64 + b) * 1024 + h]);
        s.x += p.x; s.y += p.y; s.z += p.z; s.w += p.w;
    }
    *reinterpret_cast<float4*>(&g_g[(size_t)b * 1024 + h]) = s;
}

// ---------------- scores[b,t] = enc[b,t,:] . g[b,:] + s0[b] ----------------
__global__ void __launch_bounds__(256) scores_kernel(const float* __restrict__ enc)
{
    int b = blockIdx.x >> 6;
    int t = ((blockIdx.x & 63) << 3) | (threadIdx.x >> 5);
    int lane = threadIdx.x & 31;
    const float4* e  = reinterpret_cast<const float4*>(enc + ((size_t)b * 512 + t) * 1024);
    const float4* gv = reinterpret_cast<const float4*>(g_g + (size_t)b * 1024);
    float acc = 0.f;
#pragma unroll
    for (int i = 0; i < 8; i++) {
        float4 ev = e[lane + 32 * i];
        float4 gg = gv[lane + 32 * i];
        acc += ev.x * gg.x + ev.y * gg.y + ev.z * gg.z + ev.w * gg.w;
    }
#pragma unroll
    for (int o = 16; o; o >>= 1) acc += __shfl_xor_sync(0xffffffffu, acc, o);
    if (lane == 0) g_scores[b * 512 + t] = acc + g_s0[b];
}

// ---------------- softmax over t (per b), in place ----------------
__global__ void __launch_bounds__(256) softmax_kernel()
{
    int b = blockIdx.x, tid = threadIdx.x;
    int wid = tid >> 5, lane = tid & 31;
    __shared__ float red[8];
    __shared__ float bval;

    float2 v = *reinterpret_cast<float2*>(&g_scores[b * 512 + tid * 2]);
    float mx = fmaxf(v.x, v.y);
#pragma unroll
    for (int o = 16; o; o >>= 1) mx = fmaxf(mx, __shfl_xor_sync(0xffffffffu, mx, o));
    if (lane == 0) red[wid] = mx;
    __syncthreads();
    if (tid == 0) {
        float m = red[0];
#pragma unroll
        for (int i = 1; i < 8; i++) m = fmaxf(m, red[i]);
        bval = m;
    }
    __syncthreads();
    float M = bval;
    float e0 = __expf(v.x - M), e1 = __expf(v.y - M);
    float s = e0 + e1;
    __syncthreads();
#pragma unroll
    for (int o = 16; o; o >>= 1) s += __shfl_xor_sync(0xffffffffu, s, o);
    if (lane == 0) red[wid] = s;
    __syncthreads();
    if (tid == 0) {
        float t = 0.f;
#pragma unroll
        for (int i = 0; i < 8; i++) t += red[i];
        bval = t;
    }
    __syncthreads();
    float inv = 1.f / bval;
    *reinterpret_cast<float2*>(&g_scores[b * 512 + tid * 2]) = make_float2(e0 * inv, e1 * inv);
}

// ---------------- context partials over 128-t chunks ----------------
__global__ void __launch_bounds__(256) context_kernel(const float* __restrict__ enc)
{
    int b = blockIdx.x, half = blockIdx.y, zc = blockIdx.z;
    __shared__ float w[128];
    if (threadIdx.x < 128) w[threadIdx.x] = g_scores[b * 512 + zc * 128 + threadIdx.x];
    __syncthreads();
    int h = half * 512 + threadIdx.x * 2;
    const float* ep = enc + (size_t)b * 512 * 1024 + (size_t)zc * 128 * 1024 + h;
    float2 acc = make_float2(0.f, 0.f);
#pragma unroll 4
    for (int t = 0; t < 128; t++) {
        float2 e = *reinterpret_cast<const float2*>(ep + (size_t)t * 1024);
        acc.x += w[t] * e.x;
        acc.y += w[t] * e.y;
    }
    *reinterpret_cast<float2*>(&g_ctxp[(size_t)(zc * 64 + b) * 1024 + h]) = acc;
}

__global__ void __launch_bounds__(256) ctx_reduce_kernel()
{
    int b = blockIdx.x;
    int h = threadIdx.x * 4;
    float4 s = make_float4(0.f, 0.f, 0.f, 0.f);
#pragma unroll
    for (int z = 0; z < 4; z++) {
        float4 p = *reinterpret_cast<float4*>(&g_ctxp[(size_t)(z * 64 + b) * 1024 + h]);
        s.x += p.x; s.y += p.y; s.z += p.z; s.w += p.w;
    }
    *reinterpret_cast<float4*>(&g_concat[(size_t)b * 2048 + 1024 + h]) = s;
}

// ---------------- co = tanh(sum(c1 partials) + bc) ----------------
__global__ void __launch_bounds__(256) co_epilogue_kernel(const float* __restrict__ bc)
{
    int b = blockIdx.x;
    int h = threadIdx.x * 4;
    float4 s = *reinterpret_cast<const float4*>(bc + h);
#pragma unroll
    for (int z = 0; z < NSPLIT; z++) {
        float4 p = *reinterpret_cast<float4*>(&g_c1p[(size_t)(z * 64 + b) * 1024 + h]);
        s.x += p.x; s.y += p.y; s.z += p.z; s.w += p.w;
    }
    s.x = tanhf(s.x); s.y = tanhf(s.y); s.z = tanhf(s.z); s.w = tanhf(s.w);
    *reinterpret_cast<float4*>(&g_co[(size_t)b * 1024 + h]) = s;
}

// ---------------- pack co into mma A-fragments (hi/lo bf16) ----------------
// grid 64 (kstep), 128 threads (mb = t/32, lane = t%32).
// Fragment order per PTX m16n8k16: a0=(m=gid,k..k+1) a1=(m=gid+8) a2=(m=gid,k+8) a3=(m=gid+8,k+8)
__global__ void prep_afrag_kernel()
{
    int kstep = blockIdx.x;
    int mb = threadIdx.x >> 5, lane = threadIdx.x & 31;
    int gid = lane >> 2, tig = lane & 3;
    int m0 = mb * 16 + gid;
    int k = kstep * 16 + 2 * tig;

    uint4 h, l;
    bf16_split2(g_co[m0 * 1024 + k],           g_co[m0 * 1024 + k + 1],           h.x, l.x);
    bf16_split2(g_co[(m0 + 8) * 1024 + k],     g_co[(m0 + 8) * 1024 + k + 1],     h.y, l.y);
    bf16_split2(g_co[m0 * 1024 + k + 8],       g_co[m0 * 1024 + k + 9],           h.z, l.z);
    bf16_split2(g_co[(m0 + 8) * 1024 + k + 8], g_co[(m0 + 8) * 1024 + k + 9],     h.w, l.w);

    int idx = (kstep * 4 + mb) * 32 + lane;
    g_afh[idx] = h;
    g_afl[idx] = l;
}

// ============ W_o GEMM via bf16 3-pass mma: C[64,V] = co @ Wo^T + bias ============
// grid 393 x 256 threads (8 warps, each owns 16 output cols). BK=32.
__global__ void __launch_bounds__(256)
gemm_out_mma(const float* __restrict__ W, const float* __restrict__ bias,
             float* __restrict__ C)
{
    __shared__ unsigned Wsh_h[128 * 20];   // [n][k-u32], row pitch 20 u32 (40 bf16)
    __shared__ unsigned Wsh_l[128 * 20];

    const int tid = threadIdx.x;
    const int w = tid >> 5, lane = tid & 31;
    const int gid = lane >> 2, tig = lane & 3;
    const int j0 = blockIdx.x * 128;

    float d[4][2][4];
#pragma unroll
    for (int a = 0; a < 4; a++)
#pragma unroll
        for (int b = 0; b < 2; b++)
#pragma unroll
            for (int c = 0; c < 4; c++) d[a][b][c] = 0.f;

    // W tile loader: 4 passes, pass i: f4 = i*256 + tid; row = f4>>3; kq = f4&7.
    float4 wreg[4];
#pragma unroll
    for (int i = 0; i < 4; i++) {
        int f4 = i * 256 + tid;
        int row = f4 >> 3, kq = f4 & 7;
        int gj = j0 + row;
        wreg[i] = (gj < Vdim)
            ? *reinterpret_cast<const float4*>(W + (size_t)gj * 1024 + kq * 4)
            : make_float4(0.f, 0.f, 0.f, 0.f);
    }

    for (int kt = 0; kt < 32; kt++) {
        // convert current regs -> smem (bf16 hi/lo)
#pragma unroll
        for (int i = 0; i < 4; i++) {
            int f4 = i * 256 + tid;
            int row = f4 >> 3, kq = f4 & 7;
            unsigned h0, l0, h1, l1;
            bf16_split2(wreg[i].x, wreg[i].y, h0, l0);
            bf16_split2(wreg[i].z, wreg[i].w, h1, l1);
            int u = row * 20 + kq * 2;
            Wsh_h[u] = h0; Wsh_h[u + 1] = h1;
            Wsh_l[u] = l0; Wsh_l[u + 1] = l1;
        }
        __syncthreads();

        // prefetch next tile
        if (kt < 31) {
#pragma unroll
            for (int i = 0; i < 4; i++) {
                int f4 = i * 256 + tid;
                int row = f4 >> 3, kq = f4 & 7;
                int gj = j0 + row;
                wreg[i] = (gj < Vdim)
                    ? *reinterpret_cast<const float4*>(W + (size_t)gj * 1024 + (kt + 1) * 32 + kq * 4)
                    : make_float4(0.f, 0.f, 0.f, 0.f);
            }
        }

        // mma on current tile: 2 k16 steps
#pragma unroll
        for (int s = 0; s < 2; s++) {
            int kstep = kt * 2 + s;
            unsigned bh[2][2], bl[2][2];
#pragma unroll
            for (int nb = 0; nb < 2; nb++) {
                int n = w * 16 + nb * 8 + gid;
                int u = n * 20 + s * 8 + tig;
                bh[nb][0] = Wsh_h[u]; bh[nb][1] = Wsh_h[u + 4];
                bl[nb][0] = Wsh_l[u]; bl[nb][1] = Wsh_l[u + 4];
            }
#pragma unroll
            for (int mb = 0; mb < 4; mb++) {
                int idx = (kstep * 4 + mb) * 32 + lane;
                uint4 ah = g_afh[idx];
                uint4 al = g_afl[idx];
#pragma unroll
                for (int nb = 0; nb < 2; nb++) {
                    mma_bf16(d[mb][nb], ah, bh[nb][0], bh[nb][1]);
                    mma_bf16(d[mb][nb], ah, bl[nb][0], bl[nb][1]);
                    mma_bf16(d[mb][nb], al, bh[nb][0], bh[nb][1]);
                }
            }
        }
        __syncthreads();
    }

    // epilogue: c0=(m,jc) c1=(m,jc+1) c2=(m+8,jc) c3=(m+8,jc+1)
#pragma unroll
    for (int mb = 0; mb < 4; mb++) {
        int m = mb * 16 + gid;
#pragma unroll
        for (int nb = 0; nb < 2; nb++) {
            int jc = j0 + w * 16 + nb * 8 + 2 * tig;
            if (jc < Vdim) {
                C[(size_t)m * Vdim + jc]       = d[mb][nb][0] + bias[jc];
                C[(size_t)(m + 8) * Vdim + jc] = d[mb][nb][2] + bias[jc];
            }
            if (jc + 1 < Vdim) {
                C[(size_t)m * Vdim + jc + 1]       = d[mb][nb][1] + bias[jc + 1];
                C[(size_t)(m + 8) * Vdim + jc + 1] = d[mb][nb][3] + bias[jc + 1];
            }
        }
    }
}

// ---------------- launch ----------------
extern "C" void kernel_launch(void* const* d_in, const int* in_sizes, int n_in,
                              void* d_out, int out_size)
{
    const int*   seq = (const int*)d_in[0];
    const float* h0  = (const float*)d_in[1];
    const float* enc = (const float*)d_in[2];
    const float* emb = (const float*)d_in[3];
    const float* Wih = (const float*)d_in[4];
    const float* Whh = (const float*)d_in[5];
    const float* bih = (const float*)d_in[6];
    const float* bhh = (const float*)d_in[7];
    const float* Wa  = (const float*)d_in[8];
    const float* ba  = (const float*)d_in[9];
    const float* Wc  = (const float*)d_in[10];
    const float* bc  = (const float*)d_in[11];
    const float* Wo  = (const float*)d_in[12];
    const float* bo  = (const float*)d_in[13];

    float* out = (float*)d_out;                       // [B, V]
    float* hid = out + (size_t)Bdim * Vdim;           // [1, B, H]

    float *gip, *ghp, *gp, *c1p, *concat;
    cudaGetSymbolAddress((void**)&gip, g_gip);
    cudaGetSymbolAddress((void**)&ghp, g_ghp);
    cudaGetSymbolAddress((void**)&gp, g_gp);
    cudaGetSymbolAddress((void**)&c1p, g_c1p);
    cudaGetSymbolAddress((void**)&concat, g_concat);

    // GRU input/hidden GEMMs, split-K x8 (K=1024, 128 per split), dual-set
    gemm_nt_part<<<dim3(48, 2, NSPLIT), 256>>>(emb, seq, Wih, gip,
                                               Hdim, 3 * Hdim, Hdim, Hdim / NSPLIT,
                                               h0, Whh, ghp);
    // gates: reduce partials + biases + nonlinearity -> h
    gate_kernel<<<256, 256>>>(h0, bih, bhh, hid);
    // s0 = h . b_a
    s0_kernel<<<64, 128>>>(ba);
    // g = h @ W_a (NN), split-K x8
    gemm_nn_part<<<dim3(16, 1, NSPLIT), 256>>>(concat, Wa, gp,
                                               2 * Hdim, Hdim, Hdim / NSPLIT);
    g_reduce_kernel<<<64, 256>>>();
    // scores
    scores_kernel<<<4096, 256>>>(enc);
    // softmax
    softmax_kernel<<<64, 256>>>();
    // context (t-split x4) + reduce
    context_kernel<<<dim3(64, 2, 4), 256>>>(enc);
    ctx_reduce_kernel<<<64, 256>>>();
    // c1 = concat @ Wc^T, split-K x8 (K=2048, 256 per split)
    gemm_nt_part<<<dim3(16, 1, NSPLIT), 256>>>(concat, nullptr, Wc, c1p,
                                               2 * Hdim, Hdim, 2 * Hdim, 2 * Hdim / NSPLIT,
                                               nullptr, nullptr, nullptr);
    // co = tanh(c1 + bc)
    co_epilogue_kernel<<<64, 256>>>(bc);
    // pack co into bf16 hi/lo mma fragments
    prep_afrag_kernel<<<64, 128>>>();
    // output = co @ Wo^T + bo   (bf16 3-pass tensor-core GEMM)
    gemm_out_mma<<<(Vdim + 127) / 128, 256>>>(Wo, bo, out);
}

// round 17
// speedup vs baseline: 2.4992x; 1.0521x over previous
#include <cuda_runtime.h>
#include <cuda_bf16.h>
#include <math.h>

static constexpr int Hdim = 1024;
static constexpr int Vdim = 50257;
static constexpr int Bdim = 64;
static constexpr int Tdim = 512;
static constexpr int NSPLIT = 8;    // GRU GEMMs
static constexpr int NSPLIT2 = 16;  // Wa / Wc GEMMs

// ---------------- scratch (static device arrays only) ----------------
__device__ float g_gip[NSPLIT * Bdim * 3 * Hdim];   // gi partials
__device__ float g_ghp[NSPLIT * Bdim * 3 * Hdim];   // gh partials
__device__ float g_gp [NSPLIT2 * Bdim * Hdim];      // (h@W_a) partials
__device__ float g_c1p[NSPLIT2 * Bdim * Hdim];      // (concat@Wc^T) partials
__device__ float g_concat[Bdim * 2 * Hdim];         // [:, :H] = h, [:, H:] = context
__device__ float g_g[Bdim * Hdim];                  // h @ W_a
__device__ float g_s0[Bdim];                        // h . b_a
__device__ float g_scores[Bdim * Tdim];             // scores -> attn weights (in place)
__device__ float g_ctxp[4 * Bdim * Hdim];           // context partials (t-split)
__device__ float g_co[Bdim * Hdim];                 // concat_output
__device__ uint4 g_afh[64 * 4 * 32];                // co hi bf16 mma A-fragments
__device__ uint4 g_afl[64 * 4 * 32];                // co lo bf16 mma A-fragments

// ---------------- f32x2 helpers ----------------
__device__ __forceinline__ unsigned long long pack_dup(float a) {
    unsigned long long r;
    asm("mov.b64 %0, {%1, %1};" : "=l"(r) : "f"(a));
    return r;
}
__device__ __forceinline__ void fma2(unsigned long long& d, unsigned long long a,
                                     unsigned long long b) {
    asm("fma.rn.f32x2 %0, %1, %2, %3;" : "=l"(d) : "l"(a), "l"(b), "l"(d));
}
__device__ __forceinline__ float2 unpack2(unsigned long long v) {
    float2 f;
    f.x = __uint_as_float((unsigned)(v & 0xFFFFFFFFull));
    f.y = __uint_as_float((unsigned)(v >> 32));
    return f;
}

// ---------------- bf16 split helpers ----------------
__device__ __forceinline__ void bf16_split2(float x, float y, unsigned& hi, unsigned& lo) {
    __nv_bfloat16 hx = __float2bfloat16(x);
    __nv_bfloat16 hy = __float2bfloat16(y);
    __nv_bfloat16 lx = __float2bfloat16(x - __bfloat162float(hx));
    __nv_bfloat16 ly = __float2bfloat16(y - __bfloat162float(hy));
    hi = (unsigned)__bfloat16_as_ushort(hx) | ((unsigned)__bfloat16_as_ushort(hy) << 16);
    lo = (unsigned)__bfloat16_as_ushort(lx) | ((unsigned)__bfloat16_as_ushort(ly) << 16);
}

__device__ __forceinline__ void mma_bf16(float (&d)[4], const uint4& a,
                                         unsigned b0, unsigned b1) {
    asm volatile(
        "mma.sync.aligned.m16n8k16.row.col.f32.bf16.bf16.f32 "
        "{%0,%1,%2,%3}, {%4,%5,%6,%7}, {%8,%9}, {%0,%1,%2,%3};"
        : "+f"(d[0]), "+f"(d[1]), "+f"(d[2]), "+f"(d[3])
        : "r"(a.x), "r"(a.y), "r"(a.z), "r"(a.w), "r"(b0), "r"(b1));
}

// ============ split-K NT partial GEMM: Cp[z] = A[64,Kslice] @ W[N,K]^T slice ============
__global__ void __launch_bounds__(256)
gemm_nt_part(const float* __restrict__ A, const int* __restrict__ gidx,
             const float* __restrict__ W, float* __restrict__ Cp,
             int lda, int N, int K, int Kper,
             const float* A2, const float* W2, float* Cp2)
{
    if (blockIdx.y == 1) { A = A2; W = W2; Cp = Cp2; gidx = nullptr; }

    __shared__ float As[32][66];
    __shared__ float Ws[32][66];

    const int tid = threadIdx.x;
    const int tx = tid & 15, ty = tid >> 4;
    const int j0 = blockIdx.x * 64;
    const int kb = blockIdx.z * Kper;

    unsigned long long acc[4][2];
#pragma unroll
    for (int i = 0; i < 4; i++) { acc[i][0] = 0ull; acc[i][1] = 0ull; }

    const int mload = tid >> 3;
    const int qload = tid & 7;

    for (int k0 = kb; k0 < kb + Kper; k0 += 32) {
#pragma unroll
        for (int it = 0; it < 2; it++) {
            int mm = mload + 32 * it;
            const float* arow = gidx ? (A + (size_t)gidx[mm] * lda)
                                     : (A + (size_t)mm * lda);
            float4 v = *reinterpret_cast<const float4*>(arow + k0 + qload * 4);
            As[qload * 4 + 0][mm] = v.x; As[qload * 4 + 1][mm] = v.y;
            As[qload * 4 + 2][mm] = v.z; As[qload * 4 + 3][mm] = v.w;

            float4 w4 = *reinterpret_cast<const float4*>(W + (size_t)(j0 + mm) * K + k0 + qload * 4);
            Ws[qload * 4 + 0][mm] = w4.x; Ws[qload * 4 + 1][mm] = w4.y;
            Ws[qload * 4 + 2][mm] = w4.z; Ws[qload * 4 + 3][mm] = w4.w;
        }
        __syncthreads();
#pragma unroll
        for (int kk = 0; kk < 32; kk++) {
            float2 a01 = *reinterpret_cast<const float2*>(&As[kk][ty * 4]);
            float2 a23 = *reinterpret_cast<const float2*>(&As[kk][ty * 4 + 2]);
            unsigned long long b0 =
                __double_as_longlong(*reinterpret_cast<const double*>(&Ws[kk][tx * 4]));
            unsigned long long b1 =
                __double_as_longlong(*reinterpret_cast<const double*>(&Ws[kk][tx * 4 + 2]));
            unsigned long long a0 = pack_dup(a01.x), a1 = pack_dup(a01.y);
            unsigned long long a2 = pack_dup(a23.x), a3 = pack_dup(a23.y);
            fma2(acc[0][0], a0, b0); fma2(acc[0][1], a0, b1);
            fma2(acc[1][0], a1, b0); fma2(acc[1][1], a1, b1);
            fma2(acc[2][0], a2, b0); fma2(acc[2][1], a2, b1);
            fma2(acc[3][0], a3, b0); fma2(acc[3][1], a3, b1);
        }
        __syncthreads();
    }

    float* base = Cp + (size_t)blockIdx.z * 64 * N;
#pragma unroll
    for (int i = 0; i < 4; i++) {
        int m = ty * 4 + i;
        float2 c01 = unpack2(acc[i][0]);
        float2 c23 = unpack2(acc[i][1]);
        float4 v = make_float4(c01.x, c01.y, c23.x, c23.y);
        *reinterpret_cast<float4*>(base + (size_t)m * N + j0 + tx * 4) = v;
    }
}

// ============ split-K NN partial GEMM: Cp[z] = A[64,Kslice] @ W[Kslice,N] ============
__global__ void __launch_bounds__(256)
gemm_nn_part(const float* __restrict__ A, const float* __restrict__ W,
             float* __restrict__ Cp, int lda, int N, int Kper)
{
    __shared__ float As[32][66];
    __shared__ float Ws[32][66];

    const int tid = threadIdx.x;
    const int tx = tid & 15, ty = tid >> 4;
    const int j0 = blockIdx.x * 64;
    const int kb = blockIdx.z * Kper;

    unsigned long long acc[4][2];
#pragma unroll
    for (int i = 0; i < 4; i++) { acc[i][0] = 0ull; acc[i][1] = 0ull; }

    const int mload = tid >> 3;
    const int qload = tid & 7;
    const int jq = tid & 15;
    const int kr = tid >> 4;

    for (int k0 = kb; k0 < kb + Kper; k0 += 32) {
#pragma unroll
        for (int it = 0; it < 2; it++) {
            int mm = mload + 32 * it;
            float4 v = *reinterpret_cast<const float4*>(A + (size_t)mm * lda + k0 + qload * 4);
            As[qload * 4 + 0][mm] = v.x; As[qload * 4 + 1][mm] = v.y;
            As[qload * 4 + 2][mm] = v.z; As[qload * 4 + 3][mm] = v.w;

            int kk = kr + 16 * it;
            float4 w4 = *reinterpret_cast<const float4*>(W + (size_t)(k0 + kk) * N + j0 + jq * 4);
            *reinterpret_cast<float2*>(&Ws[kk][jq * 4])     = make_float2(w4.x, w4.y);
            *reinterpret_cast<float2*>(&Ws[kk][jq * 4 + 2]) = make_float2(w4.z, w4.w);
        }
        __syncthreads();
#pragma unroll
        for (int kk = 0; kk < 32; kk++) {
            float2 a01 = *reinterpret_cast<const float2*>(&As[kk][ty * 4]);
            float2 a23 = *reinterpret_cast<const float2*>(&As[kk][ty * 4 + 2]);
            unsigned long long b0 =
                __double_as_longlong(*reinterpret_cast<const double*>(&Ws[kk][tx * 4]));
            unsigned long long b1 =
                __double_as_longlong(*reinterpret_cast<const double*>(&Ws[kk][tx * 4 + 2]));
            unsigned long long a0 = pack_dup(a01.x), a1 = pack_dup(a01.y);
            unsigned long long a2 = pack_dup(a23.x), a3 = pack_dup(a23.y);
            fma2(acc[0][0], a0, b0); fma2(acc[0][1], a0, b1);
            fma2(acc[1][0], a1, b0); fma2(acc[1][1], a1, b1);
            fma2(acc[2][0], a2, b0); fma2(acc[2][1], a2, b1);
            fma2(acc[3][0], a3, b0); fma2(acc[3][1], a3, b1);
        }
        __syncthreads();
    }

    float* base = Cp + (size_t)blockIdx.z * 64 * N;
#pragma unroll
    for (int i = 0; i < 4; i++) {
        int m = ty * 4 + i;
        float2 c01 = unpack2(acc[i][0]);
        float2 c23 = unpack2(acc[i][1]);
        float4 v = make_float4(c01.x, c01.y, c23.x, c23.y);
        *reinterpret_cast<float4*>(base + (size_t)m * N + j0 + tx * 4) = v;
    }
}

// ---------------- GRU gates: reduce split-K partials + bias + nonlinearity ----------------
__global__ void gate_kernel(const float* __restrict__ h0,
                            const float* __restrict__ bih, const float* __restrict__ bhh,
                            float* __restrict__ hid_out)
{
    int i = blockIdx.x * blockDim.x + threadIdx.x;   // 0..65535
    int b = i >> 10, c = i & 1023;
    float gir = bih[c], giz = bih[1024 + c], gin = bih[2048 + c];
    float ghr = bhh[c], ghz = bhh[1024 + c], ghn = bhh[2048 + c];
#pragma unroll
    for (int s = 0; s < NSPLIT; s++) {
        const float* gp = g_gip + (size_t)(s * 64 + b) * 3072;
        const float* hp = g_ghp + (size_t)(s * 64 + b) * 3072;
        gir += gp[c]; giz += gp[1024 + c]; gin += gp[2048 + c];
        ghr += hp[c]; ghz += hp[1024 + c]; ghn += hp[2048 + c];
    }
    float r = 1.f / (1.f + __expf(-(gir + ghr)));
    float z = 1.f / (1.f + __expf(-(giz + ghz)));
    float n = tanhf(gin + r * ghn);
    float hv = (1.f - z) * n + z * h0[i];
    g_concat[(size_t)b * 2048 + c] = hv;
    hid_out[i] = hv;
}

// ---------------- s0[b] = h[b] . b_a ----------------
__global__ void s0_kernel(const float* __restrict__ ba)
{
    int b = blockIdx.x;
    float p = 0.f;
    for (int h = threadIdx.x; h < 1024; h += 128)
        p += g_concat[(size_t)b * 2048 + h] * ba[h];
#pragma unroll
    for (int o = 16; o; o >>= 1) p += __shfl_xor_sync(0xffffffffu, p, o);
    __shared__ float red[4];
    int wid = threadIdx.x >> 5, lane = threadIdx.x & 31;
    if (lane == 0) red[wid] = p;
    __syncthreads();
    if (threadIdx.x == 0) g_s0[b] = red[0] + red[1] + red[2] + red[3];
}

// ---------------- reduce g partials -> g_g ----------------
__global__ void __launch_bounds__(256) g_reduce_kernel()
{
    int b = blockIdx.x;
    int h = threadIdx.x * 4;
    float4 s = make_float4(0.f, 0.f, 0.f, 0.f);
#pragma unroll
    for (int z = 0; z < NSPLIT2; z++) {
        float4 p = *reinterpret_cast<float4*>(&g_gp[(size_t)(z * 64 + b) * 1024 + h]);
        s.x += p.x; s.y += p.y; s.z += p.z; s.w += p.w;
    }
    *reinterpret_cast<float4*>(&g_g[(size_t)b * 1024 + h]) = s;
}

// ---------------- scores[b,t] = enc[b,t,:] . g[b,:] + s0[b] ----------------
__global__ void __launch_bounds__(256) scores_kernel(const float* __restrict__ enc)
{
    int b = blockIdx.x >> 6;
    int t = ((blockIdx.x & 63) << 3) | (threadIdx.x >> 5);
    int lane = threadIdx.x & 31;
    const float4* e  = reinterpret_cast<const float4*>(enc + ((size_t)b * 512 + t) * 1024);
    const float4* gv = reinterpret_cast<const float4*>(g_g + (size_t)b * 1024);
    float acc = 0.f;
#pragma unroll
    for (int i = 0; i < 8; i++) {
        float4 ev = e[lane + 32 * i];
        float4 gg = gv[lane + 32 * i];
        acc += ev.x * gg.x + ev.y * gg.y + ev.z * gg.z + ev.w * gg.w;
    }
#pragma unroll
    for (int o = 16; o; o >>= 1) acc += __shfl_xor_sync(0xffffffffu, acc, o);
    if (lane == 0) g_scores[b * 512 + t] = acc + g_s0[b];
}

// ---------------- softmax over t (per b), in place ----------------
__global__ void __launch_bounds__(256) softmax_kernel()
{
    int b = blockIdx.x, tid = threadIdx.x;
    int wid = tid >> 5, lane = tid & 31;
    __shared__ float red[8];
    __shared__ float bval;

    float2 v = *reinterpret_cast<float2*>(&g_scores[b * 512 + tid * 2]);
    float mx = fmaxf(v.x, v.y);
#pragma unroll
    for (int o = 16; o; o >>= 1) mx = fmaxf(mx, __shfl_xor_sync(0xffffffffu, mx, o));
    if (lane == 0) red[wid] = mx;
    __syncthreads();
    if (tid == 0) {
        float m = red[0];
#pragma unroll
        for (int i = 1; i < 8; i++) m = fmaxf(m, red[i]);
        bval = m;
    }
    __syncthreads();
    float M = bval;
    float e0 = __expf(v.x - M), e1 = __expf(v.y - M);
    float s = e0 + e1;
    __syncthreads();
#pragma unroll
    for (int o = 16; o; o >>= 1) s += __shfl_xor_sync(0xffffffffu, s, o);
    if (lane == 0) red[wid] = s;
    __syncthreads();
    if (tid == 0) {
        float t = 0.f;
#pragma unroll
        for (int i = 0; i < 8; i++) t += red[i];
        bval = t;
    }
    __syncthreads();
    float inv = 1.f / bval;
    *reinterpret_cast<float2*>(&g_scores[b * 512 + tid * 2]) = make_float2(e0 * inv, e1 * inv);
}

// ---------------- context partials over 128-t chunks ----------------
__global__ void __launch_bounds__(256) context_kernel(const float* __restrict__ enc)
{
    int b = blockIdx.x, half = blockIdx.y, zc = blockIdx.z;
    __shared__ float w[128];
    if (threadIdx.x < 128) w[threadIdx.x] = g_scores[b * 512 + zc * 128 + threadIdx.x];
    __syncthreads();
    int h = half * 512 + threadIdx.x * 2;
    const float* ep = enc + (size_t)b * 512 * 1024 + (size_t)zc * 128 * 1024 + h;
    float2 acc = make_float2(0.f, 0.f);
#pragma unroll 4
    for (int t = 0; t < 128; t++) {
        float2 e = *reinterpret_cast<const float2*>(ep + (size_t)t * 1024);
        acc.x += w[t] * e.x;
        acc.y += w[t] * e.y;
    }
    *reinterpret_cast<float2*>(&g_ctxp[(size_t)(zc * 64 + b) * 1024 + h]) = acc;
}

__global__ void __launch_bounds__(256) ctx_reduce_kernel()
{
    int b = blockIdx.x;
    int h = threadIdx.x * 4;
    float4 s = make_float4(0.f, 0.f, 0.f, 0.f);
#pragma unroll
    for (int z = 0; z < 4; z++) {
        float4 p = *reinterpret_cast<float4*>(&g_ctxp[(size_t)(z * 64 + b) * 1024 + h]);
        s.x += p.x; s.y += p.y; s.z += p.z; s.w += p.w;
    }
    *reinterpret_cast<float4*>(&g_concat[(size_t)b * 2048 + 1024 + h]) = s;
}

// ---------------- co = tanh(sum(c1 partials) + bc) ----------------
__global__ void __launch_bounds__(256) co_epilogue_kernel(const float* __restrict__ bc)
{
    int b = blockIdx.x;
    int h = threadIdx.x * 4;
    float4 s = *reinterpret_cast<const float4*>(bc + h);
#pragma unroll
    for (int z = 0; z < NSPLIT2; z++) {
        float4 p = *reinterpret_cast<float4*>(&g_c1p[(size_t)(z * 64 + b) * 1024 + h]);
        s.x += p.x; s.y += p.y; s.z += p.z; s.w += p.w;
    }
    s.x = tanhf(s.x); s.y = tanhf(s.y); s.z = tanhf(s.z); s.w = tanhf(s.w);
    *reinterpret_cast<float4*>(&g_co[(size_t)b * 1024 + h]) = s;
}

// ---------------- pack co into mma A-fragments (hi/lo bf16) ----------------
__global__ void prep_afrag_kernel()
{
    int kstep = blockIdx.x;
    int mb = threadIdx.x >> 5, lane = threadIdx.x & 31;
    int gid = lane >> 2, tig = lane & 3;
    int m0 = mb * 16 + gid;
    int k = kstep * 16 + 2 * tig;

    uint4 h, l;
    bf16_split2(g_co[m0 * 1024 + k],           g_co[m0 * 1024 + k + 1],           h.x, l.x);
    bf16_split2(g_co[(m0 + 8) * 1024 + k],     g_co[(m0 + 8) * 1024 + k + 1],     h.y, l.y);
    bf16_split2(g_co[m0 * 1024 + k + 8],       g_co[m0 * 1024 + k + 9],           h.z, l.z);
    bf16_split2(g_co[(m0 + 8) * 1024 + k + 8], g_co[(m0 + 8) * 1024 + k + 9],     h.w, l.w);

    int idx = (kstep * 4 + mb) * 32 + lane;
    g_afh[idx] = h;
    g_afl[idx] = l;
}

// ============ W_o GEMM via bf16 3-pass mma: C[64,V] = co @ Wo^T + bias ============
// grid 197 x 256 threads (8 warps, each owns 32 output cols). Block tile N=256, BK=32.
// nb=4 halves A-fragment L1 traffic per mma vs the nb=2 version.
__global__ void __launch_bounds__(256, 2)
gemm_out_mma(const float* __restrict__ W, const float* __restrict__ bias,
             float* __restrict__ C)
{
    __shared__ unsigned Wsh_h[256 * 20];   // [n][k-u32], row pitch 20 u32 (40 bf16)
    __shared__ unsigned Wsh_l[256 * 20];

    const int tid = threadIdx.x;
    const int w = tid >> 5, lane = tid & 31;
    const int gid = lane >> 2, tig = lane & 3;
    const int j0 = blockIdx.x * 256;

    float d[4][4][4];
#pragma unroll
    for (int a = 0; a < 4; a++)
#pragma unroll
        for (int b = 0; b < 4; b++)
#pragma unroll
            for (int c = 0; c < 4; c++) d[a][b][c] = 0.f;

    for (int kt = 0; kt < 32; kt++) {
        // load + convert W tile: 256 rows x 32 k; thread handles 8 float4 chunks
#pragma unroll
        for (int i = 0; i < 8; i++) {
            int f4 = i * 256 + tid;
            int row = f4 >> 3, kq = f4 & 7;
            int gj = j0 + row;
            float4 v = (gj < Vdim)
                ? *reinterpret_cast<const float4*>(W + (size_t)gj * 1024 + kt * 32 + kq * 4)
                : make_float4(0.f, 0.f, 0.f, 0.f);
            unsigned h0, l0, h1, l1;
            bf16_split2(v.x, v.y, h0, l0);
            bf16_split2(v.z, v.w, h1, l1);
            int u = row * 20 + kq * 2;
            Wsh_h[u] = h0; Wsh_h[u + 1] = h1;
            Wsh_l[u] = l0; Wsh_l[u + 1] = l1;
        }
        __syncthreads();

#pragma unroll
        for (int s = 0; s < 2; s++) {
            int kstep = kt * 2 + s;
            unsigned bh[4][2], bl[4][2];
#pragma unroll
            for (int nb = 0; nb < 4; nb++) {
                int n = w * 32 + nb * 8 + gid;
                int u = n * 20 + s * 8 + tig;
                bh[nb][0] = Wsh_h[u]; bh[nb][1] = Wsh_h[u + 4];
                bl[nb][0] = Wsh_l[u]; bl[nb][1] = Wsh_l[u + 4];
            }
#pragma unroll
            for (int mb = 0; mb < 4; mb++) {
                int idx = (kstep * 4 + mb) * 32 + lane;
                uint4 ah = g_afh[idx];
                uint4 al = g_afl[idx];
#pragma unroll
                for (int nb = 0; nb < 4; nb++) {
                    mma_bf16(d[mb][nb], ah, bh[nb][0], bh[nb][1]);
                    mma_bf16(d[mb][nb], ah, bl[nb][0], bl[nb][1]);
                    mma_bf16(d[mb][nb], al, bh[nb][0], bh[nb][1]);
                }
            }
        }
        __syncthreads();
    }

    // epilogue: c0=(m,jc) c1=(m,jc+1) c2=(m+8,jc) c3=(m+8,jc+1)
#pragma unroll
    for (int mb = 0; mb < 4; mb++) {
        int m = mb * 16 + gid;
#pragma unroll
        for (int nb = 0; nb < 4; nb++) {
            int jc = j0 + w * 32 + nb * 8 + 2 * tig;
            if (jc < Vdim) {
                C[(size_t)m * Vdim + jc]       = d[mb][nb][0] + bias[jc];
                C[(size_t)(m + 8) * Vdim + jc] = d[mb][nb][2] + bias[jc];
            }
            if (jc + 1 < Vdim) {
                C[(size_t)m * Vdim + jc + 1]       = d[mb][nb][1] + bias[jc + 1];
                C[(size_t)(m + 8) * Vdim + jc + 1] = d[mb][nb][3] + bias[jc + 1];
            }
        }
    }
}

// ---------------- launch ----------------
extern "C" void kernel_launch(void* const* d_in, const int* in_sizes, int n_in,
                              void* d_out, int out_size)
{
    const int*   seq = (const int*)d_in[0];
    const float* h0  = (const float*)d_in[1];
    const float* enc = (const float*)d_in[2];
    const float* emb = (const float*)d_in[3];
    const float* Wih = (const float*)d_in[4];
    const float* Whh = (const float*)d_in[5];
    const float* bih = (const float*)d_in[6];
    const float* bhh = (const float*)d_in[7];
    const float* Wa  = (const float*)d_in[8];
    const float* ba  = (const float*)d_in[9];
    const float* Wc  = (const float*)d_in[10];
    const float* bc  = (const float*)d_in[11];
    const float* Wo  = (const float*)d_in[12];
    const float* bo  = (const float*)d_in[13];

    float* out = (float*)d_out;                       // [B, V]
    float* hid = out + (size_t)Bdim * Vdim;           // [1, B, H]

    float *gip, *ghp, *gp, *c1p, *concat;
    cudaGetSymbolAddress((void**)&gip, g_gip);
    cudaGetSymbolAddress((void**)&ghp, g_ghp);
    cudaGetSymbolAddress((void**)&gp, g_gp);
    cudaGetSymbolAddress((void**)&c1p, g_c1p);
    cudaGetSymbolAddress((void**)&concat, g_concat);

    // GRU input/hidden GEMMs, split-K x8 (K=1024, 128 per split), dual-set
    gemm_nt_part<<<dim3(48, 2, NSPLIT), 256>>>(emb, seq, Wih, gip,
                                               Hdim, 3 * Hdim, Hdim, Hdim / NSPLIT,
                                               h0, Whh, ghp);
    // gates: reduce partials + biases + nonlinearity -> h
    gate_kernel<<<256, 256>>>(h0, bih, bhh, hid);
    // s0 = h . b_a
    s0_kernel<<<64, 128>>>(ba);
    // g = h @ W_a (NN), split-K x16 (K=1024, 64 per split)
    gemm_nn_part<<<dim3(16, 1, NSPLIT2), 256>>>(concat, Wa, gp,
                                                2 * Hdim, Hdim, Hdim / NSPLIT2);
    g_reduce_kernel<<<64, 256>>>();
    // scores
    scores_kernel<<<4096, 256>>>(enc);
    // softmax
    softmax_kernel<<<64, 256>>>();
    // context (t-split x4) + reduce
    context_kernel<<<dim3(64, 2, 4), 256>>>(enc);
    ctx_reduce_kernel<<<64, 256>>>();
    // c1 = concat @ Wc^T, split-K x16 (K=2048, 128 per split)
    gemm_nt_part<<<dim3(16, 1, NSPLIT2), 256>>>(concat, nullptr, Wc, c1p,
                                                2 * Hdim, Hdim, 2 * Hdim, 2 * Hdim / NSPLIT2,
                                                nullptr, nullptr, nullptr);
    // co = tanh(c1 + bc)
    co_epilogue_kernel<<<64, 256>>>(bc);
    // pack co into bf16 hi/lo mma fragments
    prep_afrag_kernel<<<64, 128>>>();
    // output = co @ Wo^T + bo   (bf16 3-pass tensor-core GEMM, N=256 tiles)
    gemm_out_mma<<<(Vdim + 255) / 256, 256>>>(Wo, bo, out);
}